// round 1
// baseline (speedup 1.0000x reference)
#include <cuda_runtime.h>
#include <cuda_bf16.h>

// Problem constants
#define NROWS 16384   // B*S
#define KDIM  512     // H
#define NCOLS 640     // G*V
#define VDIM  320     // V
#define DG    128     // D/G
#define OUT_ELEMS (NROWS * 256)  // B*S*D

// Scratch (device globals; no allocation allowed)
__device__ float g_logits[NROWS * NCOLS];   // ~42 MB
__device__ float g_marginal[NCOLS];

// ---------------------------------------------------------------------------
// Kernel 1: SGEMM  logits = X @ W + b
// X [16384,512] row-major, W [512,640] row-major.
// Tile: 128 (M) x 128 (N) x 16 (K), 256 threads, 8x8 per thread,
// double-buffered shared memory.
// Grid: (5, 128)  -> blockIdx.x = N tile, blockIdx.y = M tile.
// ---------------------------------------------------------------------------
__global__ __launch_bounds__(256)
void gemm_bias_kernel(const float* __restrict__ X,
                      const float* __restrict__ W,
                      const float* __restrict__ bias) {
    __shared__ float As[2][16][132];   // [k][m], padded to kill store conflicts
    __shared__ float Bs[2][16][128];   // [k][n]

    const int tid = threadIdx.x;
    const int m0 = blockIdx.y * 128;
    const int n0 = blockIdx.x * 128;
    const int tx = tid & 15;           // N direction
    const int ty = tid >> 4;           // M direction

    // A load mapping: 512 float4 per tile, 2 per thread
    const int am  = tid >> 2;          // 0..63
    const int akq = (tid & 3) * 4;     // k offset 0,4,8,12
    const float* Aptr = X + (size_t)(m0 + am) * KDIM + akq;

    // B load mapping: 512 float4 per tile, 2 per thread
    const int bk = tid >> 5;           // 0..7
    const int bn = (tid & 31) * 4;     // 0..124
    const float* Bptr = W + (size_t)bk * NCOLS + n0 + bn;

    float4 a0, a1, b0, b1;

    // Preload tile 0
    a0 = *(const float4*)(Aptr);
    a1 = *(const float4*)(Aptr + 64 * KDIM);
    b0 = *(const float4*)(Bptr);
    b1 = *(const float4*)(Bptr + 8 * NCOLS);

    As[0][akq + 0][am] = a0.x;  As[0][akq + 1][am] = a0.y;
    As[0][akq + 2][am] = a0.z;  As[0][akq + 3][am] = a0.w;
    As[0][akq + 0][am + 64] = a1.x;  As[0][akq + 1][am + 64] = a1.y;
    As[0][akq + 2][am + 64] = a1.z;  As[0][akq + 3][am + 64] = a1.w;
    *(float4*)&Bs[0][bk][bn]     = b0;
    *(float4*)&Bs[0][bk + 8][bn] = b1;
    __syncthreads();

    float acc[8][8];
    #pragma unroll
    for (int i = 0; i < 8; i++)
        #pragma unroll
        for (int j = 0; j < 8; j++) acc[i][j] = 0.0f;

    const int KTILES = KDIM / 16;  // 32
    for (int kt = 0; kt < KTILES; kt++) {
        const int cur = kt & 1;
        const int nxt = cur ^ 1;

        if (kt < KTILES - 1) {
            const float* Ap = Aptr + (kt + 1) * 16;
            const float* Bp = Bptr + (size_t)(kt + 1) * 16 * NCOLS;
            a0 = *(const float4*)(Ap);
            a1 = *(const float4*)(Ap + 64 * KDIM);
            b0 = *(const float4*)(Bp);
            b1 = *(const float4*)(Bp + 8 * NCOLS);
        }

        #pragma unroll
        for (int k = 0; k < 16; k++) {
            float ar[8], br[8];
            *(float4*)(ar)     = *(const float4*)&As[cur][k][ty * 8];
            *(float4*)(ar + 4) = *(const float4*)&As[cur][k][ty * 8 + 4];
            *(float4*)(br)     = *(const float4*)&Bs[cur][k][tx * 8];
            *(float4*)(br + 4) = *(const float4*)&Bs[cur][k][tx * 8 + 4];
            #pragma unroll
            for (int i = 0; i < 8; i++)
                #pragma unroll
                for (int j = 0; j < 8; j++)
                    acc[i][j] = fmaf(ar[i], br[j], acc[i][j]);
        }

        if (kt < KTILES - 1) {
            As[nxt][akq + 0][am] = a0.x;  As[nxt][akq + 1][am] = a0.y;
            As[nxt][akq + 2][am] = a0.z;  As[nxt][akq + 3][am] = a0.w;
            As[nxt][akq + 0][am + 64] = a1.x;  As[nxt][akq + 1][am + 64] = a1.y;
            As[nxt][akq + 2][am + 64] = a1.z;  As[nxt][akq + 3][am + 64] = a1.w;
            *(float4*)&Bs[nxt][bk][bn]     = b0;
            *(float4*)&Bs[nxt][bk + 8][bn] = b1;
            __syncthreads();
        }
    }

    // Epilogue: add bias, store logits
    float bb[8];
    *(float4*)(bb)     = *(const float4*)(bias + n0 + tx * 8);
    *(float4*)(bb + 4) = *(const float4*)(bias + n0 + tx * 8 + 4);
    #pragma unroll
    for (int i = 0; i < 8; i++) {
        float* orow = g_logits + (size_t)(m0 + ty * 8 + i) * NCOLS + n0 + tx * 8;
        float4 v0, v1;
        v0.x = acc[i][0] + bb[0]; v0.y = acc[i][1] + bb[1];
        v0.z = acc[i][2] + bb[2]; v0.w = acc[i][3] + bb[3];
        v1.x = acc[i][4] + bb[4]; v1.y = acc[i][5] + bb[5];
        v1.z = acc[i][6] + bb[6]; v1.w = acc[i][7] + bb[7];
        *(float4*)(orow)     = v0;
        *(float4*)(orow + 4) = v1;
    }
}

// ---------------------------------------------------------------------------
// Kernel 2: zero the marginal accumulator (graph is replayed; must reset)
// ---------------------------------------------------------------------------
__global__ void zero_marg_kernel() {
    g_marginal[threadIdx.x] = 0.0f;
}

// ---------------------------------------------------------------------------
// Kernel 3: per-(n,g) argmax + softmax + gather + marginal accumulation.
// One warp handles 4 rows of one group. CTA = 256 threads = 8 warps
// -> 16 rows x 2 groups per CTA. Grid = 1024.
// ---------------------------------------------------------------------------
__global__ __launch_bounds__(256)
void row_kernel(const float* __restrict__ gumbels,
                const int*   __restrict__ mask,
                const float* __restrict__ codevectors,
                float* __restrict__ out) {
    __shared__ float smarg[NCOLS];
    const int tid = threadIdx.x;
    for (int j = tid; j < NCOLS; j += 256) smarg[j] = 0.0f;
    __syncthreads();

    const int warp = tid >> 5;
    const int lane = tid & 31;
    const int g = warp & 1;
    const int nbase = blockIdx.x * 16 + (warp >> 1) * 4;

    for (int r = 0; r < 4; r++) {
        const int n = nbase + r;
        const float* lrow = g_logits + (size_t)n * NCOLS + g * VDIM;
        const float* grow = gumbels  + (size_t)n * NCOLS + g * VDIM;  // same flat layout

        float l[10];
        float lmax = -1e30f;
        float gmax = -1e30f;
        int   gidx = 0;
        #pragma unroll
        for (int i = 0; i < 10; i++) {
            const int v = lane + 32 * i;
            l[i] = lrow[v];
            const float gv = l[i] + grow[v];
            lmax = fmaxf(lmax, l[i]);
            if (gv > gmax) { gmax = gv; gidx = v; }
        }
        // warp-reduce max of logits (for softmax)
        #pragma unroll
        for (int o = 16; o > 0; o >>= 1)
            lmax = fmaxf(lmax, __shfl_xor_sync(0xffffffffu, lmax, o));
        // warp-reduce argmax of logit+gumbel, ties -> lowest index (jnp.argmax)
        #pragma unroll
        for (int o = 16; o > 0; o >>= 1) {
            const float ov = __shfl_xor_sync(0xffffffffu, gmax, o);
            const int   oi = __shfl_xor_sync(0xffffffffu, gidx, o);
            if (ov > gmax || (ov == gmax && oi < gidx)) { gmax = ov; gidx = oi; }
        }
        // softmax of raw logits
        float e[10];
        float s = 0.0f;
        #pragma unroll
        for (int i = 0; i < 10; i++) { e[i] = __expf(l[i] - lmax); s += e[i]; }
        #pragma unroll
        for (int o = 16; o > 0; o >>= 1)
            s += __shfl_xor_sync(0xffffffffu, s, o);
        const float inv = 1.0f / s;

        if (mask[n] != 0) {
            #pragma unroll
            for (int i = 0; i < 10; i++)
                atomicAdd(&smarg[g * VDIM + lane + 32 * i], e[i] * inv);
        }

        // gather the selected codevector row: 128 floats = 32 float4
        const float4* cb = (const float4*)(codevectors + (size_t)(g * VDIM + gidx) * DG);
        float4* o4 = (float4*)(out + (size_t)n * 256 + g * DG);
        o4[lane] = cb[lane];
    }

    __syncthreads();
    for (int j = tid; j < NCOLS; j += 256)
        atomicAdd(&g_marginal[j], smarg[j]);
}

// ---------------------------------------------------------------------------
// Kernel 4: perplexity finalize. One CTA, 640 threads.
// ---------------------------------------------------------------------------
__global__ void finalize_kernel(const int* __restrict__ mask,
                                float* __restrict__ out, int out_size) {
    __shared__ float red[NCOLS];
    __shared__ float s_msum;
    const int tid = threadIdx.x;

    float c = 0.0f;
    for (int i = tid; i < NROWS; i += NCOLS) c += (mask[i] != 0) ? 1.0f : 0.0f;
    red[tid] = c;
    __syncthreads();
    if (tid == 0) {
        float s = 0.0f;
        for (int i = 0; i < NCOLS; i++) s += red[i];
        s_msum = s;
    }
    __syncthreads();

    const float p = g_marginal[tid] / s_msum;
    red[tid] = p * logf(p + 1e-7f);
    __syncthreads();

    if (tid == 0) {
        float e0 = 0.0f, e1 = 0.0f;
        for (int i = 0; i < VDIM; i++)       e0 += red[i];
        for (int i = VDIM; i < NCOLS; i++)   e1 += red[i];
        const float perp = expf(-e0) + expf(-e1);
        if (out_size > OUT_ELEMS) out[OUT_ELEMS] = perp;
    }
}

// ---------------------------------------------------------------------------
extern "C" void kernel_launch(void* const* d_in, const int* in_sizes, int n_in,
                              void* d_out, int out_size) {
    const float* X    = (const float*)d_in[0];  // hidden_states [8,2048,512]
    const int*   mask = (const int*)  d_in[1];  // mask_time_indices [8,2048]
    const float* W    = (const float*)d_in[2];  // W_proj [512,640]
    const float* b    = (const float*)d_in[3];  // b_proj [640]
    const float* cb   = (const float*)d_in[4];  // codevectors [1,640,128]
    const float* gum  = (const float*)d_in[5];  // gumbels [32768,320]
    float* out = (float*)d_out;

    dim3 ggrid(NCOLS / 128, NROWS / 128);  // (5, 128)
    gemm_bias_kernel<<<ggrid, 256>>>(X, W, b);
    zero_marg_kernel<<<1, NCOLS>>>();
    row_kernel<<<NROWS / 16, 256>>>(gum, mask, cb, out);
    finalize_kernel<<<1, NCOLS>>>(mask, out, out_size);
}